// round 3
// baseline (speedup 1.0000x reference)
#include <cuda_runtime.h>

#define HH 2048
#define WW 2048
#define TPB 256
#define WARPS 8
#define OPW 62                 // output columns per warp (64 loaded, 62 owned)
#define ROWS 16                // output rows per strip
#define GRID_X 5               // ceil(34 active warp-columns / 8)
#define GRID_Y (HH / ROWS)     // 128
#define NBLOCKS (GRID_X * GRID_Y)   // 640

__device__ float g_acc[3];     // zeroed at load; reset by last block each replay
__device__ unsigned g_count;

__global__ __launch_bounds__(TPB) void loss_fused_kernel(
    const float* __restrict__ pred_E,
    const float* __restrict__ pred_v,
    const float* __restrict__ strain,
    float* __restrict__ out)
{
    const int tid  = threadIdx.x;
    const int lane = tid & 31;
    const int warp = tid >> 5;
    const int wg   = blockIdx.x * WARPS + warp;      // global warp-column id
    const int base = wg * OPW;                        // first input col of this warp
    const int c0   = base + 2 * lane;                 // lane's even column
    const int row0 = blockIdx.y * ROWS;
    const bool colok = (c0 < WW);                     // c0 even => c0+1 < WW too
    const bool owner = (lane < 31) && colok;          // owns cols c0,c0+1 for sum(E)

    float accx = 0.f, accy = 0.f, accE = 0.f;

    if (base < WW) {
        // vertical rings, per column j in {0,1}
        float h3E_a0=0,h3E_a1=0, h3E_b0=0,h3E_b1=0;
        float h3XX_a0=0,h3XX_a1=0, h3XX_b0=0,h3XX_b1=0;
        float yy0_a0=0,yy0_a1=0, yy0_b0=0,yy0_b1=0;
        float yy2_a0=0,yy2_a1=0, yy2_b0=0,yy2_b1=0;
        float xy0_a0=0,xy0_a1=0, xy0_b0=0,xy0_b1=0;
        float xy2_a0=0,xy2_a1=0, xy2_b0=0,xy2_b1=0;

        // current-row raw registers
        float cE0,cE1,cV0,cV1,cXX0,cYY0,cXY0,cXX1,cYY1,cXY1;
        {
            const int idx = row0 * WW + c0;
            float2 e2 = colok ? *(const float2*)(pred_E + idx) : make_float2(0.f,0.f);
            float2 v2 = colok ? *(const float2*)(pred_v + idx) : make_float2(0.f,0.f);
            float2 sa = colok ? *(const float2*)(strain + 3*idx)     : make_float2(0.f,0.f);
            float2 sb = colok ? *(const float2*)(strain + 3*idx + 2) : make_float2(0.f,0.f);
            float2 sc = colok ? *(const float2*)(strain + 3*idx + 4) : make_float2(0.f,0.f);
            cE0=e2.x; cE1=e2.y; cV0=v2.x; cV1=v2.y;
            cXX0=sa.x; cYY0=sa.y; cXY0=sb.x;
            cXX1=sb.y; cYY1=sc.x; cXY1=sc.y;
        }

        #pragma unroll 2
        for (int k = 0; k < ROWS + 2; ++k) {
            const int r = row0 + k;

            // ---- prefetch raw row r+1 ----
            float nE0=0,nE1=0,nV0=0,nV1=0,nXX0r=0,nYY0r=0,nXY0r=0,nXX1r=0,nYY1r=0,nXY1r=0;
            if (k < ROWS + 1) {
                const bool ok = (r + 1 < HH) && colok;
                const int idx = (r + 1) * WW + c0;
                if (ok) {
                    float2 e2 = *(const float2*)(pred_E + idx);
                    float2 v2 = *(const float2*)(pred_v + idx);
                    float2 sa = *(const float2*)(strain + 3*idx);
                    float2 sb = *(const float2*)(strain + 3*idx + 2);
                    float2 sc = *(const float2*)(strain + 3*idx + 4);
                    nE0=e2.x; nE1=e2.y; nV0=v2.x; nV1=v2.y;
                    nXX0r=sa.x; nYY0r=sa.y; nXY0r=sb.x;
                    nXX1r=sb.y; nYY1r=sc.x; nXY1r=sc.y;
                }
            }

            // ---- stress, both columns ----
            const float fr0 = __fdividef(cE0, 1.f - cV0 * cV0);
            const float sxx0 = (cXX0 + cV0 * cYY0) * fr0;
            const float syy0 = (cV0 * cXX0 + cYY0) * fr0;
            const float sxy0 = cXY0 * (1.f - cV0) * 0.5f * fr0;
            const float fr1 = __fdividef(cE1, 1.f - cV1 * cV1);
            const float sxx1 = (cXX1 + cV1 * cYY1) * fr1;
            const float syy1 = (cV1 * cXX1 + cYY1) * fr1;
            const float sxy1 = cXY1 * (1.f - cV1) * 0.5f * fr1;

            if (owner && k < ROWS) accE += cE0 + cE1;

            // ---- neighbor-lane leading pair via shuffle (8 SHFLs) ----
            const float nbE0  = __shfl_down_sync(0xFFFFFFFFu, cE0,  1);
            const float nbE1  = __shfl_down_sync(0xFFFFFFFFu, cE1,  1);
            const float nbXX0 = __shfl_down_sync(0xFFFFFFFFu, sxx0, 1);
            const float nbXX1 = __shfl_down_sync(0xFFFFFFFFu, sxx1, 1);
            const float nbYY0 = __shfl_down_sync(0xFFFFFFFFu, syy0, 1);
            const float nbYY1 = __shfl_down_sync(0xFFFFFFFFu, syy1, 1);
            const float nbXY0 = __shfl_down_sync(0xFFFFFFFFu, sxy0, 1);
            const float nbXY1 = __shfl_down_sync(0xFFFFFFFFu, sxy1, 1);

            // horizontal 3-sums for this row
            const float h3E0  = cE0 + cE1 + nbE0;
            const float h3E1  = cE1 + nbE0 + nbE1;
            const float h3XX0 = sxx0 + sxx1 + nbXX0;
            const float h3XX1 = sxx1 + nbXX0 + nbXX1;

            if (k >= 2 && lane < 31 && r < HH) {
                // column 0 output at c0
                if (c0 < WW - 2) {
                    const float Econv = h3E_a0 + h3E_b0 + h3E0;
                    const float fx = (h3XX0 - h3XX_a0)
                                   + (xy0_a0 + xy0_b0 + sxy0)
                                   - (xy2_a0 + xy2_b0 + nbXY0);
                    const float h3XYc = sxy0 + sxy1 + nbXY0;
                    const float h3XYa = xy0_a0 + xy0_a1 + xy2_a0;
                    const float fy = (yy0_a0 + yy0_b0 + syy0)
                                   - (yy2_a0 + yy2_b0 + nbYY0)
                                   + (h3XYc - h3XYa);
                    const float inv = __fdividef(1.f, Econv);
                    accx += fabsf(fx * inv);
                    accy += fabsf(fy * inv);
                }
                // column 1 output at c0+1
                if (c0 + 1 < WW - 2) {
                    const float Econv = h3E_a1 + h3E_b1 + h3E1;
                    const float fx = (h3XX1 - h3XX_a1)
                                   + (xy0_a1 + xy0_b1 + sxy1)
                                   - (xy2_a1 + xy2_b1 + nbXY1);
                    const float h3XYc = sxy1 + nbXY0 + nbXY1;
                    const float h3XYa = xy0_a1 + xy2_a0 + xy2_a1;
                    const float fy = (yy0_a1 + yy0_b1 + syy1)
                                   - (yy2_a1 + yy2_b1 + nbYY1)
                                   + (h3XYc - h3XYa);
                    const float inv = __fdividef(1.f, Econv);
                    accx += fabsf(fx * inv);
                    accy += fabsf(fy * inv);
                }
            }

            // ---- rotate rings ----
            h3E_a0 = h3E_b0;  h3E_b0 = h3E0;   h3E_a1 = h3E_b1;  h3E_b1 = h3E1;
            h3XX_a0 = h3XX_b0; h3XX_b0 = h3XX0; h3XX_a1 = h3XX_b1; h3XX_b1 = h3XX1;
            yy0_a0 = yy0_b0;  yy0_b0 = syy0;   yy0_a1 = yy0_b1;  yy0_b1 = syy1;
            yy2_a0 = yy2_b0;  yy2_b0 = nbYY0;  yy2_a1 = yy2_b1;  yy2_b1 = nbYY1;
            xy0_a0 = xy0_b0;  xy0_b0 = sxy0;   xy0_a1 = xy0_b1;  xy0_b1 = sxy1;
            xy2_a0 = xy2_b0;  xy2_b0 = nbXY0;  xy2_a1 = xy2_b1;  xy2_b1 = nbXY1;

            cE0=nE0; cE1=nE1; cV0=nV0; cV1=nV1;
            cXX0=nXX0r; cYY0=nYY0r; cXY0=nXY0r;
            cXX1=nXX1r; cYY1=nYY1r; cXY1=nXY1r;
        }
    }

    // ---- block reduction ----
    __shared__ float red[WARPS][3];
    __shared__ bool isLast;
    #pragma unroll
    for (int o = 16; o > 0; o >>= 1) {
        accx += __shfl_down_sync(0xFFFFFFFFu, accx, o);
        accy += __shfl_down_sync(0xFFFFFFFFu, accy, o);
        accE += __shfl_down_sync(0xFFFFFFFFu, accE, o);
    }
    if (lane == 0) { red[warp][0] = accx; red[warp][1] = accy; red[warp][2] = accE; }
    __syncthreads();
    if (warp == 0) {
        float ax = (lane < WARPS) ? red[lane][0] : 0.f;
        float ay = (lane < WARPS) ? red[lane][1] : 0.f;
        float aE = (lane < WARPS) ? red[lane][2] : 0.f;
        #pragma unroll
        for (int o = 4; o > 0; o >>= 1) {
            ax += __shfl_down_sync(0xFFFFFFFFu, ax, o);
            ay += __shfl_down_sync(0xFFFFFFFFu, ay, o);
            aE += __shfl_down_sync(0xFFFFFFFFu, aE, o);
        }
        if (lane == 0) {
            atomicAdd(&g_acc[0], ax);
            atomicAdd(&g_acc[1], ay);
            atomicAdd(&g_acc[2], aE);
        }
    }

    // ---- last-block finalize (resets state for next graph replay) ----
    if (tid == 0) {
        __threadfence();
        unsigned prev = atomicAdd(&g_count, 1u);
        isLast = (prev == NBLOCKS - 1);
    }
    __syncthreads();
    if (isLast && tid == 0) {
        const float invM = 1.0f / ((float)(WW - 2) * (float)(HH - 2));
        const float invN = 1.0f / ((float)WW * (float)HH);
        out[0] = g_acc[0] * invM + g_acc[1] * invM
               + fabsf(g_acc[2] * invN - 1.0f) * 0.01f;
        g_acc[0] = 0.f; g_acc[1] = 0.f; g_acc[2] = 0.f;
        g_count = 0u;
    }
}

extern "C" void kernel_launch(void* const* d_in, const int* in_sizes, int n_in,
                              void* d_out, int out_size) {
    const float* pred_E = (const float*)d_in[0];
    const float* pred_v = (const float*)d_in[1];
    const float* strain = (const float*)d_in[2];

    dim3 grid(GRID_X, GRID_Y);   // 5 x 128 = 640 blocks
    loss_fused_kernel<<<grid, TPB>>>(pred_E, pred_v, strain, (float*)d_out);
}

// round 6
// speedup vs baseline: 1.0831x; 1.0831x over previous
#include <cuda_runtime.h>

#define HH 2048
#define WW 2048
#define TPB 256
#define WARPS (TPB / 32)
#define CPW 30                         // output columns per warp
#define CPB (WARPS * CPW)              // 240 output columns per block
#define ROWS 16                        // output rows per strip
#define GRID_X ((WW - 2 + CPB - 1) / CPB)   // 9
#define GRID_Y (HH / ROWS)                  // 128
#define NBLOCKS (GRID_X * GRID_Y)           // 1152

__device__ float g_acc[3];       // zero-initialized at module load; reset by last block
__device__ unsigned g_count;

__global__ __launch_bounds__(TPB) void loss_fused_kernel(
    const float* __restrict__ pred_E,
    const float* __restrict__ pred_v,
    const float* __restrict__ strain,
    float* __restrict__ out)
{
    const int tid  = threadIdx.x;
    const int lane = tid & 31;
    const int warp = tid >> 5;
    const int col  = (blockIdx.x * WARPS + warp) * CPW + lane;  // input column
    const int row0 = blockIdx.y * ROWS;
    const bool col_ok  = (col < WW);
    const bool own_col = (lane < CPW) && col_ok;      // unique owner of this column (for sum E)
    const bool out_col = (lane < CPW) && (col < WW - 2);

    float accx = 0.f, accy = 0.f, accE = 0.f;

    // register ring: rows i (a) and i+1 (b) of the running vertical sums
    float h3E_a = 0.f, h3E_b = 0.f;
    float h3XX_a = 0.f, h3XX_b = 0.f;
    float h3XY_a = 0.f, h3XY_b = 0.f;
    float yy0_a = 0.f, yy0_b = 0.f, yy2_a = 0.f, yy2_b = 0.f;
    float xy0_a = 0.f, xy0_b = 0.f, xy2_a = 0.f, xy2_b = 0.f;

    // raw prefetch registers
    float cE, cV, cXX, cYY, cXY;     // current row raw inputs
    {
        const bool ok = col_ok;      // row0 < HH always
        const int idx = row0 * WW + col;
        cE  = ok ? pred_E[idx] : 0.f;
        cV  = ok ? pred_v[idx] : 0.f;
        cXX = ok ? strain[3 * idx + 0] : 0.f;
        cYY = ok ? strain[3 * idx + 1] : 0.f;
        cXY = ok ? strain[3 * idx + 2] : 0.f;
    }

    #pragma unroll 2
    for (int k = 0; k < ROWS + 2; ++k) {
        const int r = row0 + k;

        // ---- prefetch raw row r+1 ----
        float nE = 0.f, nV = 0.f, nXX = 0.f, nYY = 0.f, nXY = 0.f;
        if (k < ROWS + 1) {
            const bool ok = (r + 1 < HH) && col_ok;
            const int idx = (r + 1) * WW + col;
            if (ok) {
                nE  = pred_E[idx];
                nV  = pred_v[idx];
                nXX = strain[3 * idx + 0];
                nYY = strain[3 * idx + 1];
                nXY = strain[3 * idx + 2];
            }
        }

        // ---- stress for current row ----
        const float frac = __fdividef(cE, 1.f - cV * cV);
        const float sxx = (cXX + cV * cYY) * frac;
        const float syy = (cV * cXX + cYY) * frac;
        const float sxy = cXY * (1.f - cV) * 0.5f * frac;

        if (own_col && k < ROWS) accE += cE;

        // ---- horizontal gathers via shuffle ----
        const float E1  = __shfl_down_sync(0xFFFFFFFFu, cE,  1);
        const float E2  = __shfl_down_sync(0xFFFFFFFFu, cE,  2);
        const float XX1 = __shfl_down_sync(0xFFFFFFFFu, sxx, 1);
        const float XX2 = __shfl_down_sync(0xFFFFFFFFu, sxx, 2);
        const float XY1 = __shfl_down_sync(0xFFFFFFFFu, sxy, 1);
        const float XY2 = __shfl_down_sync(0xFFFFFFFFu, sxy, 2);
        const float YY2 = __shfl_down_sync(0xFFFFFFFFu, syy, 2);

        const float h3E  = cE  + E1  + E2;
        const float h3XX = sxx + XX1 + XX2;
        const float h3XY = sxy + XY1 + XY2;

        if (k >= 2) {
            const int i = r - 2;                       // output row
            if (out_col && i < HH - 2) {
                const float Econv = h3E_a + h3E_b + h3E;
                const float fx = (h3XX - h3XX_a)
                               + (xy0_a + xy0_b + sxy) - (xy2_a + xy2_b + XY2);
                const float fy = (yy0_a + yy0_b + syy) - (yy2_a + yy2_b + YY2)
                               + (h3XY - h3XY_a);
                const float inv = __fdividef(1.f, Econv);   // E>0 => Econv>0
                accx += fabsf(fx * inv);
                accy += fabsf(fy * inv);
            }
        }

        // rotate rings
        h3E_a  = h3E_b;  h3E_b  = h3E;
        h3XX_a = h3XX_b; h3XX_b = h3XX;
        h3XY_a = h3XY_b; h3XY_b = h3XY;
        yy0_a  = yy0_b;  yy0_b  = syy;
        yy2_a  = yy2_b;  yy2_b  = YY2;
        xy0_a  = xy0_b;  xy0_b  = sxy;
        xy2_a  = xy2_b;  xy2_b  = XY2;

        cE = nE; cV = nV; cXX = nXX; cYY = nYY; cXY = nXY;
    }

    // ---- block reduction ----
    __shared__ float red[WARPS][3];
    __shared__ bool isLast;
    #pragma unroll
    for (int o = 16; o > 0; o >>= 1) {
        accx += __shfl_down_sync(0xFFFFFFFFu, accx, o);
        accy += __shfl_down_sync(0xFFFFFFFFu, accy, o);
        accE += __shfl_down_sync(0xFFFFFFFFu, accE, o);
    }
    if (lane == 0) { red[warp][0] = accx; red[warp][1] = accy; red[warp][2] = accE; }
    __syncthreads();
    if (warp == 0) {
        float ax = (lane < WARPS) ? red[lane][0] : 0.f;
        float ay = (lane < WARPS) ? red[lane][1] : 0.f;
        float aE = (lane < WARPS) ? red[lane][2] : 0.f;
        #pragma unroll
        for (int o = 4; o > 0; o >>= 1) {
            ax += __shfl_down_sync(0xFFFFFFFFu, ax, o);
            ay += __shfl_down_sync(0xFFFFFFFFu, ay, o);
            aE += __shfl_down_sync(0xFFFFFFFFu, aE, o);
        }
        if (lane == 0) {
            atomicAdd(&g_acc[0], ax);
            atomicAdd(&g_acc[1], ay);
            atomicAdd(&g_acc[2], aE);
        }
    }

    // ---- last-block finalize (single-kernel; resets state for next graph replay) ----
    if (tid == 0) {
        __threadfence();
        unsigned prev = atomicAdd(&g_count, 1u);
        isLast = (prev == NBLOCKS - 1);
    }
    __syncthreads();
    if (isLast && tid == 0) {
        const float invM = 1.0f / ((float)(WW - 2) * (float)(HH - 2));
        const float invN = 1.0f / ((float)WW * (float)HH);
        out[0] = g_acc[0] * invM + g_acc[1] * invM
               + fabsf(g_acc[2] * invN - 1.0f) * 0.01f;
        g_acc[0] = 0.f; g_acc[1] = 0.f; g_acc[2] = 0.f;
        g_count = 0u;
    }
}

extern "C" void kernel_launch(void* const* d_in, const int* in_sizes, int n_in,
                              void* d_out, int out_size) {
    const float* pred_E = (const float*)d_in[0];
    const float* pred_v = (const float*)d_in[1];
    const float* strain = (const float*)d_in[2];

    dim3 grid(GRID_X, GRID_Y);   // 9 x 128 = 1152 blocks
    loss_fused_kernel<<<grid, TPB>>>(pred_E, pred_v, strain, (float*)d_out);
}